// round 13
// baseline (speedup 1.0000x reference)
#include <cuda_runtime.h>
#include <math.h>

#define NP 16384
#define BB 4

static constexpr size_t F1 = (size_t)BB * 128 * NP;  // 8,388,608 floats

static constexpr size_t OFF_XN   = 0;
static constexpr size_t OFF_YN   = F1;        // reused for z = ln(xatt) later
static constexpr size_t OFF_B1   = 2 * F1;    // q pre-dw
static constexpr size_t OFF_Q    = 3 * F1;
static constexpr size_t OFF_KVP  = 4 * F1;    // 2*F1
static constexpr size_t OFF_KV   = 6 * F1;    // 2*F1
static constexpr size_t OFF_WEFF = 8 * F1;    // per-batch composed po@attn weights
static constexpr size_t OFF_XATT = 9 * F1;
static constexpr size_t OFF_TPRE = 10 * F1;                       // 680ch
static constexpr size_t OFF_T    = OFF_TPRE + (size_t)BB*680*NP;
static constexpr size_t OFF_X12  = OFF_T    + (size_t)BB*680*NP;  // 340ch
static constexpr size_t OFF_ATTN = OFF_X12  + (size_t)BB*340*NP;  // 4*8*16*16
static constexpr size_t OFF_QSS  = OFF_ATTN + 8192;               // 512
static constexpr size_t OFF_KSS  = OFF_QSS  + 512;                // 512
static constexpr size_t OFF_PART = OFF_KSS  + 512;                // 512 gate partials
static constexpr size_t OFF_QKP  = OFF_PART + 512;                // 32*64*256 qk partials
static constexpr size_t OFF_SSQP_Q  = OFF_QKP + (size_t)32 * 64 * 256;  // 512*8
static constexpr size_t OFF_SSQP_KV = OFF_SSQP_Q + 4096;                // 1024*8
static constexpr size_t SCRATCH_TOTAL = OFF_SSQP_KV + 8192;

__device__ float g_scratch[SCRATCH_TOTAL];
__device__ int   g_dk;

// dynamic smem layout for gemm_pb: AsF (32*132 u32) | BsF (16*16*66 u32) | lnS (8*32 float2)
static constexpr int PB_ASF_U32 = 32 * 132;          // 4224
static constexpr int PB_BSF_U32 = 16 * 16 * 66;      // 16896
static constexpr int PB_SMEM_BYTES = (PB_ASF_U32 + PB_BSF_U32) * 4 + 8 * 32 * 8;  // 86528

__device__ __forceinline__ unsigned f2tf32(float f) {
    unsigned r;
    asm("cvt.rna.tf32.f32 %0, %1;" : "=r"(r) : "f"(f));
    return r;
}

// ---------------- LayerNorm over channel axis (C=128), NCHW ----------------
__global__ void ln_kernel(const float* __restrict__ in_ptr, size_t in_off, size_t out_off,
                          const float* __restrict__ w, const float* __restrict__ bp)
{
    int p = blockIdx.x * blockDim.x + threadIdx.x;   // pixel within batch
    int b = blockIdx.y;
    const float* ip = (in_ptr ? in_ptr : g_scratch + in_off) + (size_t)b * 128 * NP + p;
    float s = 0.f, ss = 0.f;
    #pragma unroll 8
    for (int c = 0; c < 128; c++) { float v = ip[(size_t)c * NP]; s += v; ss += v * v; }
    float mu  = s * (1.f / 128.f);
    float var = ss * (1.f / 128.f) - mu * mu;
    float inv = rsqrtf(var + 1e-6f);
    float* op = g_scratch + out_off + (size_t)b * 128 * NP + p;
    #pragma unroll 8
    for (int c = 0; c < 128; c++) {
        float v = ip[(size_t)c * NP];
        op[(size_t)c * NP] = w[c] * ((v - mu) * inv) + bp[c];
    }
}

// ---------------- persistent-B tf32 GEMM (K=128 fixed) ------------------------
// B panel (128k x 128n) loaded ONCE into smem fragment-order; m-tiles looped
// inside the CTA so B global reads are not amplified by M/128.
// rflag: 0 none, 1 residual from resid_ptr, 2 residual from scratch+resid_off
// lnflag: 1 -> (po path, M=128) also write YN = LayerNorm(out) to yn_off.
__global__ __launch_bounds__(256, 2)
void gemm_pb(const float* __restrict__ Wp, size_t w_off, size_t wstride,
             size_t in_off, int in_cs,
             float* __restrict__ out_ptr, size_t out_off,
             int M,
             const float* __restrict__ resid_ptr, size_t resid_off, int rflag,
             int lnflag, const float* __restrict__ lnw, const float* __restrict__ lnb,
             size_t yn_off)
{
    extern __shared__ unsigned smem_u[];
    unsigned* AsF = smem_u;                       // [kblk(4)][mblk(8)] frag [32 lane x 4 reg], stride 132
    unsigned* BsF = smem_u + PB_ASF_U32;          // [kblk(16)][nblk(16)] frag [32 lane x 2 reg], stride 66
    float2* lnS = (float2*)(smem_u + PB_ASF_U32 + PB_BSF_U32);   // [8][32]

    constexpr int K = 128;
    int b = blockIdx.z;
    const float* W = (Wp ? Wp : (const float*)(g_scratch + w_off)) + (size_t)b * wstride;
    const float* in = g_scratch + in_off + (size_t)b * in_cs * NP;
    float* out = (out_ptr ? out_ptr : g_scratch + out_off) + (size_t)b * M * NP;
    const float* res = nullptr;
    if (rflag == 1)      res = resid_ptr + (size_t)b * M * NP;
    else if (rflag == 2) res = g_scratch + resid_off + (size_t)b * M * NP;

    int n0 = blockIdx.x * 128;
    int t = threadIdx.x;
    int lane = t & 31, wid = t >> 5;
    int wm = (wid & 1) * 64;        // warp m offset in tile
    int wn = (wid >> 1) * 32;       // warp n offset in tile
    int gid = lane >> 2, tig = lane & 3;

    // ---- load the FULL B panel (K=128 x 128 px) into fragment order, once ----
    #pragma unroll
    for (int i = 0; i < 16; i++) {
        int lin = t + i * 256;                // 0..4095
        int kk = lin >> 5, nq = lin & 31;     // kk 0..127, nq 0..31 (4 n each)
        float4 v4 = *(const float4*)&in[(size_t)kk * NP + n0 + nq * 4];
        int blk = (kk >> 3) * 16 + (nq >> 1);
        int regb = (kk & 7) >> 2;
        unsigned* dst = &BsF[blk * 66 + (((nq & 1) << 4) + (kk & 3)) * 2 + regb];
        dst[0]  = f2tf32(v4.x);
        dst[8]  = f2tf32(v4.y);
        dst[16] = f2tf32(v4.z);
        dst[24] = f2tf32(v4.w);
    }
    // (first __syncthreads below covers these stores)

    int MT = (M + 127) >> 7;
    for (int mt = 0; mt < MT; mt++) {
        int m0 = mt << 7;
        float acc[4][4][4];
        #pragma unroll
        for (int i = 0; i < 4; i++)
            #pragma unroll
            for (int j = 0; j < 4; j++)
                #pragma unroll
                for (int r = 0; r < 4; r++) acc[i][j][r] = 0.f;

        for (int kt = 0; kt < 4; kt++) {
            int k0 = kt << 5;
            // ---- A chunk: LDG + cvt + STS into fragment order ----
            #pragma unroll
            for (int i = 0; i < 4; i++) {
                int lin = t + i * 256;            // 0..1023
                int m = lin >> 3, kq = lin & 7;   // m 0..127, kq 0..7 (4 k each)
                int gm = m0 + m, gk = k0 + kq * 4;
                float v0 = 0.f, v1 = 0.f, v2 = 0.f, v3 = 0.f;
                if (gm < M) {
                    float4 w4 = *(const float4*)&W[(size_t)gm * K + gk];
                    v0 = w4.x; v1 = w4.y; v2 = w4.z; v3 = w4.w;
                }
                int fb = (kq >> 1) * 8 + (m >> 4);
                int regb = ((m & 15) >> 3) + ((kq & 1) << 1);
                unsigned* dst = &AsF[fb * 132 + ((m & 7) << 4) + regb];
                dst[0]  = f2tf32(v0);
                dst[4]  = f2tf32(v1);
                dst[8]  = f2tf32(v2);
                dst[12] = f2tf32(v3);
            }
            __syncthreads();

            #pragma unroll
            for (int ks = 0; ks < 4; ks++) {
                int kbg = kt * 4 + ks;            // global 8-k block 0..15
                unsigned af[4][4], bf[4][2];
                #pragma unroll
                for (int mi = 0; mi < 4; mi++) {
                    int fb = ks * 8 + (wm >> 4) + mi;
                    uint4 av = *(const uint4*)&AsF[fb * 132 + lane * 4];
                    af[mi][0] = av.x; af[mi][1] = av.y; af[mi][2] = av.z; af[mi][3] = av.w;
                }
                #pragma unroll
                for (int ni = 0; ni < 4; ni++) {
                    int blk = kbg * 16 + (wn >> 3) + ni;
                    uint2 bv = *(const uint2*)&BsF[blk * 66 + lane * 2];
                    bf[ni][0] = bv.x; bf[ni][1] = bv.y;
                }
                #pragma unroll
                for (int mi = 0; mi < 4; mi++)
                    #pragma unroll
                    for (int ni = 0; ni < 4; ni++) {
                        asm volatile(
                            "mma.sync.aligned.m16n8k8.row.col.f32.tf32.tf32.f32 "
                            "{%0,%1,%2,%3}, {%4,%5,%6,%7}, {%8,%9}, {%0,%1,%2,%3};"
                            : "+f"(acc[mi][ni][0]), "+f"(acc[mi][ni][1]),
                              "+f"(acc[mi][ni][2]), "+f"(acc[mi][ni][3])
                            : "r"(af[mi][0]), "r"(af[mi][1]), "r"(af[mi][2]), "r"(af[mi][3]),
                              "r"(bf[ni][0]), "r"(bf[ni][1]));
                    }
            }
            __syncthreads();
        }

        if (!lnflag) {
            #pragma unroll
            for (int mi = 0; mi < 4; mi++) {
                int row0 = m0 + wm + mi * 16 + gid;
                int row1 = row0 + 8;
                #pragma unroll
                for (int ni = 0; ni < 4; ni++) {
                    int col = n0 + wn + ni * 8 + tig * 2;
                    if (row0 < M) {
                        float2 v = make_float2(acc[mi][ni][0], acc[mi][ni][1]);
                        if (res) {
                            float2 r = *(const float2*)&res[(size_t)row0 * NP + col];
                            v.x += r.x; v.y += r.y;
                        }
                        *(float2*)&out[(size_t)row0 * NP + col] = v;
                    }
                    if (row1 < M) {
                        float2 v = make_float2(acc[mi][ni][2], acc[mi][ni][3]);
                        if (res) {
                            float2 r = *(const float2*)&res[(size_t)row1 * NP + col];
                            v.x += r.x; v.y += r.y;
                        }
                        *(float2*)&out[(size_t)row1 * NP + col] = v;
                    }
                }
            }
        } else {
            // ---- po epilogue: write xatt AND yn = LayerNorm(xatt). M=128, m0=0. ----
            float* ynp = g_scratch + yn_off + (size_t)b * 128 * NP;
            float s[4][2], q2[4][2];
            #pragma unroll
            for (int ni = 0; ni < 4; ni++) { s[ni][0] = s[ni][1] = 0.f; q2[ni][0] = q2[ni][1] = 0.f; }

            #pragma unroll
            for (int mi = 0; mi < 4; mi++) {
                int row0 = wm + mi * 16 + gid;
                int row1 = row0 + 8;
                #pragma unroll
                for (int ni = 0; ni < 4; ni++) {
                    int col = n0 + wn + ni * 8 + tig * 2;
                    float2 r0v = *(const float2*)&res[(size_t)row0 * NP + col];
                    float2 r1v = *(const float2*)&res[(size_t)row1 * NP + col];
                    acc[mi][ni][0] += r0v.x; acc[mi][ni][1] += r0v.y;
                    acc[mi][ni][2] += r1v.x; acc[mi][ni][3] += r1v.y;
                    *(float2*)&out[(size_t)row0 * NP + col] = make_float2(acc[mi][ni][0], acc[mi][ni][1]);
                    *(float2*)&out[(size_t)row1 * NP + col] = make_float2(acc[mi][ni][2], acc[mi][ni][3]);
                    s[ni][0]  += acc[mi][ni][0] + acc[mi][ni][2];
                    s[ni][1]  += acc[mi][ni][1] + acc[mi][ni][3];
                    q2[ni][0] += acc[mi][ni][0] * acc[mi][ni][0] + acc[mi][ni][2] * acc[mi][ni][2];
                    q2[ni][1] += acc[mi][ni][1] * acc[mi][ni][1] + acc[mi][ni][3] * acc[mi][ni][3];
                }
            }
            #pragma unroll
            for (int mask = 4; mask <= 16; mask <<= 1) {
                #pragma unroll
                for (int ni = 0; ni < 4; ni++) {
                    s[ni][0]  += __shfl_xor_sync(0xffffffffu, s[ni][0],  mask);
                    s[ni][1]  += __shfl_xor_sync(0xffffffffu, s[ni][1],  mask);
                    q2[ni][0] += __shfl_xor_sync(0xffffffffu, q2[ni][0], mask);
                    q2[ni][1] += __shfl_xor_sync(0xffffffffu, q2[ni][1], mask);
                }
            }
            if (gid == 0) {
                #pragma unroll
                for (int ni = 0; ni < 4; ni++) {
                    lnS[wid * 32 + ni * 8 + tig * 2 + 0] = make_float2(s[ni][0], q2[ni][0]);
                    lnS[wid * 32 + ni * 8 + tig * 2 + 1] = make_float2(s[ni][1], q2[ni][1]);
                }
            }
            __syncthreads();
            float mu[4][2], inv[4][2];
            #pragma unroll
            for (int ni = 0; ni < 4; ni++) {
                #pragma unroll
                for (int c = 0; c < 2; c++) {
                    float2 other = lnS[(wid ^ 1) * 32 + ni * 8 + tig * 2 + c];
                    float ts = s[ni][c] + other.x;
                    float tq = q2[ni][c] + other.y;
                    float m_ = ts * (1.f / 128.f);
                    float var = tq * (1.f / 128.f) - m_ * m_;
                    mu[ni][c] = m_;
                    inv[ni][c] = rsqrtf(var + 1e-6f);
                }
            }
            #pragma unroll
            for (int mi = 0; mi < 4; mi++) {
                int row0 = wm + mi * 16 + gid;
                int row1 = row0 + 8;
                float lw0 = lnw[row0], lb0 = lnb[row0];
                float lw1 = lnw[row1], lb1 = lnb[row1];
                #pragma unroll
                for (int ni = 0; ni < 4; ni++) {
                    int col = n0 + wn + ni * 8 + tig * 2;
                    float y00 = lw0 * ((acc[mi][ni][0] - mu[ni][0]) * inv[ni][0]) + lb0;
                    float y01 = lw0 * ((acc[mi][ni][1] - mu[ni][1]) * inv[ni][1]) + lb0;
                    float y10 = lw1 * ((acc[mi][ni][2] - mu[ni][0]) * inv[ni][0]) + lb1;
                    float y11 = lw1 * ((acc[mi][ni][3] - mu[ni][1]) * inv[ni][1]) + lb1;
                    *(float2*)&ynp[(size_t)row0 * NP + col] = make_float2(y00, y01);
                    *(float2*)&ynp[(size_t)row1 * NP + col] = make_float2(y10, y11);
                }
            }
        }
    }
}

// ---------------- streaming tf32 GEMM (pout path, K=340) ---------------------
__global__ __launch_bounds__(256, 2)
void gemm_tf32(const float* __restrict__ Wp, size_t w_off, size_t wstride,
               size_t in_off, int in_cs,
               float* __restrict__ out_ptr, size_t out_off,
               int M, int K,
               const float* __restrict__ resid_ptr, size_t resid_off, int rflag)
{
    __shared__ unsigned AsF[32 * 132];
    __shared__ unsigned BsF[64 * 66];

    int b = blockIdx.z;
    const float* W = (Wp ? Wp : (const float*)(g_scratch + w_off)) + (size_t)b * wstride;
    const float* in = g_scratch + in_off + (size_t)b * in_cs * NP;
    float* out = (out_ptr ? out_ptr : g_scratch + out_off) + (size_t)b * M * NP;
    const float* res = nullptr;
    if (rflag == 1)      res = resid_ptr + (size_t)b * M * NP;
    else if (rflag == 2) res = g_scratch + resid_off + (size_t)b * M * NP;

    int m0 = blockIdx.y * 128, n0 = blockIdx.x * 128;
    int t = threadIdx.x;
    int lane = t & 31, wid = t >> 5;
    int wm = (wid & 1) * 64;
    int wn = (wid >> 1) * 32;
    int gid = lane >> 2, tig = lane & 3;

    float acc[4][4][4];
    #pragma unroll
    for (int i = 0; i < 4; i++)
        #pragma unroll
        for (int j = 0; j < 4; j++)
            #pragma unroll
            for (int r = 0; r < 4; r++) acc[i][j][r] = 0.f;

    int KT = (K + 31) >> 5;

    float4 bpre[4];
    #pragma unroll
    for (int i = 0; i < 4; i++) {
        int lin = t + i * 256;
        int kk = lin >> 5, nq = lin & 31;
        bpre[i] = (kk < K)
            ? *(const float4*)&in[(size_t)kk * NP + n0 + nq * 4]
            : make_float4(0.f, 0.f, 0.f, 0.f);
    }

    for (int kt = 0; kt < KT; kt++) {
        int k0 = kt << 5;
        #pragma unroll
        for (int i = 0; i < 4; i++) {
            int lin = t + i * 256;
            int m = lin >> 3, kq = lin & 7;
            int gm = m0 + m, gk = k0 + kq * 4;
            float v0 = 0.f, v1 = 0.f, v2 = 0.f, v3 = 0.f;
            if (gm < M) {
                if (gk + 3 < K) {
                    float4 w4 = *(const float4*)&W[(size_t)gm * K + gk];
                    v0 = w4.x; v1 = w4.y; v2 = w4.z; v3 = w4.w;
                } else {
                    if (gk + 0 < K) v0 = W[(size_t)gm * K + gk + 0];
                    if (gk + 1 < K) v1 = W[(size_t)gm * K + gk + 1];
                    if (gk + 2 < K) v2 = W[(size_t)gm * K + gk + 2];
                    if (gk + 3 < K) v3 = W[(size_t)gm * K + gk + 3];
                }
            }
            int fb = (kq >> 1) * 8 + (m >> 4);
            int regb = ((m & 15) >> 3) + ((kq & 1) << 1);
            unsigned* dst = &AsF[fb * 132 + ((m & 7) << 4) + regb];
            dst[0]  = f2tf32(v0);
            dst[4]  = f2tf32(v1);
            dst[8]  = f2tf32(v2);
            dst[12] = f2tf32(v3);
        }
        #pragma unroll
        for (int i = 0; i < 4; i++) {
            int lin = t + i * 256;
            int kk = lin >> 5, nq = lin & 31;
            int blk = (kk >> 3) * 16 + (nq >> 1);
            int regb = (kk & 7) >> 2;
            unsigned* dst = &BsF[blk * 66 + (((nq & 1) << 4) + (kk & 3)) * 2 + regb];
            dst[0]  = f2tf32(bpre[i].x);
            dst[8]  = f2tf32(bpre[i].y);
            dst[16] = f2tf32(bpre[i].z);
            dst[24] = f2tf32(bpre[i].w);
        }
        __syncthreads();

        if (kt + 1 < KT) {
            int kn0 = (kt + 1) << 5;
            #pragma unroll
            for (int i = 0; i < 4; i++) {
                int lin = t + i * 256;
                int kk = lin >> 5, nq = lin & 31;
                bpre[i] = (kn0 + kk < K)
                    ? *(const float4*)&in[(size_t)(kn0 + kk) * NP + n0 + nq * 4]
                    : make_float4(0.f, 0.f, 0.f, 0.f);
            }
        }

        #pragma unroll
        for (int ks = 0; ks < 4; ks++) {
            unsigned af[4][4], bf[4][2];
            #pragma unroll
            for (int mi = 0; mi < 4; mi++) {
                int fb = ks * 8 + (wm >> 4) + mi;
                uint4 av = *(const uint4*)&AsF[fb * 132 + lane * 4];
                af[mi][0] = av.x; af[mi][1] = av.y; af[mi][2] = av.z; af[mi][3] = av.w;
            }
            #pragma unroll
            for (int ni = 0; ni < 4; ni++) {
                int blk = ks * 16 + (wn >> 3) + ni;
                uint2 bv = *(const uint2*)&BsF[blk * 66 + lane * 2];
                bf[ni][0] = bv.x; bf[ni][1] = bv.y;
            }
            #pragma unroll
            for (int mi = 0; mi < 4; mi++)
                #pragma unroll
                for (int ni = 0; ni < 4; ni++) {
                    asm volatile(
                        "mma.sync.aligned.m16n8k8.row.col.f32.tf32.tf32.f32 "
                        "{%0,%1,%2,%3}, {%4,%5,%6,%7}, {%8,%9}, {%0,%1,%2,%3};"
                        : "+f"(acc[mi][ni][0]), "+f"(acc[mi][ni][1]),
                          "+f"(acc[mi][ni][2]), "+f"(acc[mi][ni][3])
                        : "r"(af[mi][0]), "r"(af[mi][1]), "r"(af[mi][2]), "r"(af[mi][3]),
                          "r"(bf[ni][0]), "r"(bf[ni][1]));
                }
        }
        __syncthreads();
    }

    #pragma unroll
    for (int mi = 0; mi < 4; mi++) {
        int row0 = m0 + wm + mi * 16 + gid;
        int row1 = row0 + 8;
        #pragma unroll
        for (int ni = 0; ni < 4; ni++) {
            int col = n0 + wn + ni * 8 + tig * 2;
            if (row0 < M) {
                float2 v = make_float2(acc[mi][ni][0], acc[mi][ni][1]);
                if (res) {
                    float2 r = *(const float2*)&res[(size_t)row0 * NP + col];
                    v.x += r.x; v.y += r.y;
                }
                *(float2*)&out[(size_t)row0 * NP + col] = v;
            }
            if (row1 < M) {
                float2 v = make_float2(acc[mi][ni][2], acc[mi][ni][3]);
                if (res) {
                    float2 r = *(const float2*)&res[(size_t)row1 * NP + col];
                    v.x += r.x; v.y += r.y;
                }
                *(float2*)&out[(size_t)row1 * NP + col] = v;
            }
        }
    }
}

// ---------------- fused gate: g1 GEMM (M=64) + g2 + sigmoid + partials --------
__global__ __launch_bounds__(256, 2)
void gate_fused(const float* __restrict__ W, const float* __restrict__ g1b,
                const float* __restrict__ g2w, const float* __restrict__ g2b)
{
    __shared__ float As[16][68];     // [k][m], 64 rows
    __shared__ float Bs[16][132];    // [k][n], 128 pixels
    __shared__ float sred[16][136];  // per-ty partials per pixel
    __shared__ float red[128];

    int b = blockIdx.y;
    int n0 = blockIdx.x * 128;
    const float* in = g_scratch + OFF_XN + (size_t)b * 128 * NP;
    int t = threadIdx.x, tx = t & 15, ty = t >> 4;

    float acc[4][8];
    #pragma unroll
    for (int i = 0; i < 4; i++)
        #pragma unroll
        for (int j = 0; j < 8; j++) acc[i][j] = 0.f;

    for (int kt = 0; kt < 8; kt++) {
        int k0 = kt * 16;
        #pragma unroll
        for (int i = 0; i < 4; i++) {
            int lin = t * 4 + i;           // 0..1023
            int m = lin >> 4, kk = lin & 15;
            As[kk][m] = W[(size_t)m * 128 + k0 + kk];
        }
        #pragma unroll
        for (int i = 0; i < 2; i++) {
            int idx = t * 2 + i;           // 0..511
            int kk = idx >> 5, nq = idx & 31;
            float4 v4 = *(const float4*)&in[(size_t)(k0 + kk) * NP + n0 + nq * 4];
            Bs[kk][nq * 4 + 0] = v4.x;
            Bs[kk][nq * 4 + 1] = v4.y;
            Bs[kk][nq * 4 + 2] = v4.z;
            Bs[kk][nq * 4 + 3] = v4.w;
        }
        __syncthreads();
        #pragma unroll
        for (int kk = 0; kk < 16; kk++) {
            float a[4], bv[8];
            #pragma unroll
            for (int i = 0; i < 4; i++) a[i] = As[kk][ty * 4 + i];
            #pragma unroll
            for (int j = 0; j < 8; j++) bv[j] = Bs[kk][tx * 8 + j];
            #pragma unroll
            for (int i = 0; i < 4; i++)
                #pragma unroll
                for (int j = 0; j < 8; j++)
                    acc[i][j] += a[i] * bv[j];
        }
        __syncthreads();
    }

    float part[8];
    #pragma unroll
    for (int j = 0; j < 8; j++) part[j] = 0.f;
    #pragma unroll
    for (int i = 0; i < 4; i++) {
        int m = ty * 4 + i;
        float gb = g1b[m], gw = g2w[m];
        #pragma unroll
        for (int j = 0; j < 8; j++)
            part[j] += gw * fmaxf(acc[i][j] + gb, 0.f);
    }
    #pragma unroll
    for (int j = 0; j < 8; j++) sred[ty][tx * 8 + j] = part[j];
    __syncthreads();

    if (t < 128) {
        float s = g2b[0];
        #pragma unroll
        for (int r = 0; r < 16; r++) s += sred[r][t];
        red[t] = 1.f / (1.f + expf(-s));
    }
    __syncthreads();
    for (int st = 64; st; st >>= 1) {
        if (t < st) red[t] += red[t + st];
        __syncthreads();
    }
    if (!t) g_scratch[OFF_PART + (size_t)b * 128 + blockIdx.x] = red[0];
}

__global__ void finish_gate()
{
    __shared__ float red[256];
    int t = threadIdx.x;
    red[t] = g_scratch[OFF_PART + t] + g_scratch[OFF_PART + t + 256];
    __syncthreads();
    for (int st = 128; st; st >>= 1) {
        if (t < st) red[t] += red[t + st];
        __syncthreads();
    }
    if (!t) {
        float mean = red[0] * (1.f / 65536.f);
        int dk = (int)(16.f * mean);               // trunc like astype(int32)
        g_dk = dk < 1 ? 1 : (dk > 16 ? 16 : dk);
    }
}

// ---------------- tiled depthwise 3x3, pad=1, with sumsq partials ------------
__global__ void dwconv_tiled(size_t in_off, size_t out_off, const float* __restrict__ wts,
                             int C, size_t ssq_off)
{
    __shared__ float tile[18][130];
    __shared__ float red[128];
    int plane = blockIdx.x;                 // b*C + c
    int c = plane % C;
    int r0 = blockIdx.y * 16;
    int x = threadIdx.x;                    // 0..127
    const float* ip = g_scratch + in_off + (size_t)plane * NP;
    float* op = g_scratch + out_off + (size_t)plane * NP;

    #pragma unroll
    for (int i = 0; i < 18; i++) {
        int y = r0 - 1 + i;
        tile[i][x + 1] = ((unsigned)y < 128u) ? ip[y * 128 + x] : 0.f;
    }
    if (x < 18) { tile[x][0] = 0.f; tile[x][129] = 0.f; }
    __syncthreads();

    const float* kp = wts + c * 9;
    float w00 = kp[0], w01 = kp[1], w02 = kp[2];
    float w10 = kp[3], w11 = kp[4], w12 = kp[5];
    float w20 = kp[6], w21 = kp[7], w22 = kp[8];

    float a0 = tile[0][x], a1 = tile[0][x + 1], a2 = tile[0][x + 2];
    float b0 = tile[1][x], b1 = tile[1][x + 1], b2 = tile[1][x + 2];
    float ssq = 0.f;
    #pragma unroll
    for (int i = 0; i < 16; i++) {
        float c0 = tile[i + 2][x], c1 = tile[i + 2][x + 1], c2 = tile[i + 2][x + 2];
        float acc = w00 * a0 + w01 * a1 + w02 * a2
                  + w10 * b0 + w11 * b1 + w12 * b2
                  + w20 * c0 + w21 * c1 + w22 * c2;
        op[(r0 + i) * 128 + x] = acc;
        ssq += acc * acc;
        a0 = b0; a1 = b1; a2 = b2;
        b0 = c0; b1 = c1; b2 = c2;
    }
    red[x] = ssq; __syncthreads();
    for (int st = 64; st; st >>= 1) {
        if (x < st) red[x] += red[x + st];
        __syncthreads();
    }
    if (!x) g_scratch[ssq_off + (size_t)plane * 8 + blockIdx.y] = red[0];
}

// ---------------- reduce 8 sumsq partials per channel ----------------
__global__ void ssq_reduce(size_t part_off, size_t out_off, int in_cs)
{
    int idx = blockIdx.x * blockDim.x + threadIdx.x;   // 0..511
    if (idx >= 512) return;
    int b = idx >> 7, c = idx & 127;
    const float* p = g_scratch + part_off + ((size_t)b * in_cs + c) * 8;
    float s = 0.f;
    #pragma unroll
    for (int r = 0; r < 8; r++) s += p[r];
    g_scratch[out_off + idx] = s;
}

// ---------------- qk partials: 16x16 over a 256-px chunk per block ------------
__global__ void qk_partial()
{
    __shared__ float qs[16][257];
    __shared__ float ks[16][257];
    int chunk = blockIdx.x, h = blockIdx.y, b = blockIdx.z;
    int n0 = chunk * 256;
    int t = threadIdx.x;
    const float* qbase = g_scratch + OFF_Q  + ((size_t)b * 128 + h * 16) * NP + n0;
    const float* kbase = g_scratch + OFF_KV + ((size_t)b * 256 + h * 16) * NP + n0;
    #pragma unroll
    for (int r = 0; r < 16; r++) {
        qs[r][t] = qbase[(size_t)r * NP + t];
        ks[r][t] = kbase[(size_t)r * NP + t];
    }
    __syncthreads();
    int c = t >> 4, d = t & 15;
    float acc = 0.f;
    #pragma unroll 8
    for (int n = 0; n < 256; n++) acc += qs[c][n] * ks[d][n];
    g_scratch[OFF_QKP + (((size_t)(b * 8 + h) * 64 + chunk) * 256) + t] = acc;
}

// ---------------- qk reduce + normalize + temperature -------------------------
__global__ void qk_reduce(const float* __restrict__ temp)
{
    int h = blockIdx.x, b = blockIdx.y;
    int t = threadIdx.x;
    float acc = 0.f;
    const float* p = g_scratch + OFF_QKP + (size_t)(b * 8 + h) * 64 * 256 + t;
    #pragma unroll 8
    for (int j = 0; j < 64; j++) acc += p[j * 256];
    int c = t >> 4, d = t & 15;
    float qn = fmaxf(sqrtf(g_scratch[OFF_QSS + b * 128 + h * 16 + c]), 1e-12f);
    float kn = fmaxf(sqrtf(g_scratch[OFF_KSS + b * 128 + h * 16 + d]), 1e-12f);
    g_scratch[OFF_ATTN + (size_t)(b * 8 + h) * 256 + t] = acc / (qn * kn) * temp[h];
}

// ---------------- dynamic top-k mask + softmax --------------------------------
__global__ void mask_softmax()
{
    int r = blockIdx.x * blockDim.x + threadIdx.x;   // 512 rows total
    if (r >= BB * 8 * 16) return;
    float* row = g_scratch + OFF_ATTN + (size_t)r * 16;
    int dk = g_dk;
    float vals[16];
    #pragma unroll
    for (int i = 0; i < 16; i++) vals[i] = row[i];
    float mx = -3.4e38f;
    bool keep[16];
    #pragma unroll
    for (int i = 0; i < 16; i++) {
        int rank = 0;
        #pragma unroll
        for (int j = 0; j < 16; j++)
            rank += (vals[j] > vals[i]) || (vals[j] == vals[i] && j < i);
        keep[i] = rank < dk;
        if (keep[i] && vals[i] > mx) mx = vals[i];
    }
    float sum = 0.f, e[16];
    #pragma unroll
    for (int i = 0; i < 16; i++) { e[i] = keep[i] ? expf(vals[i] - mx) : 0.f; sum += e[i]; }
    float isum = 1.f / sum;
    #pragma unroll
    for (int i = 0; i < 16; i++) row[i] = e[i] * isum;
}

// ---------------- W_eff[b] = po_w @ blockdiag(attn_b) ------------------------
__global__ void compose_weff(const float* __restrict__ po_w)
{
    __shared__ float at[2048];
    int b = blockIdx.x;
    int t = threadIdx.x;
    for (int i = t; i < 2048; i += 128) at[i] = g_scratch[OFF_ATTN + (size_t)b * 2048 + i];
    __syncthreads();
    int m = t;
    float* wo = g_scratch + OFF_WEFF + ((size_t)b * 128 + m) * 128;
    #pragma unroll
    for (int h = 0; h < 8; h++) {
        float pw[16];
        #pragma unroll
        for (int c = 0; c < 16; c++) pw[c] = po_w[(size_t)m * 128 + h * 16 + c];
        #pragma unroll
        for (int d = 0; d < 16; d++) {
            float acc = 0.f;
            #pragma unroll
            for (int c = 0; c < 16; c++) acc += pw[c] * at[h * 256 + c * 16 + d];
            wo[h * 16 + d] = acc;
        }
    }
}

// ---------------- fully fused IEL tail (8-row strips) -------------------------
__global__ void iel_fused(const float* __restrict__ dw_w,
                          const float* __restrict__ w1, const float* __restrict__ w2)
{
    __shared__ float raw1[12][132], raw2[12][132];
    __shared__ float t1[10][130], t2[10][130];
    int pid = blockIdx.x;                  // b*340 + c
    int b = pid / 340, c = pid % 340;
    int r0 = blockIdx.y * 8;
    int x = threadIdx.x;                   // 0..127
    const float* p1 = g_scratch + OFF_TPRE + ((size_t)b * 680 + c) * NP;
    const float* p2 = p1 + (size_t)340 * NP;

    #pragma unroll
    for (int i = 0; i < 12; i++) {
        int y = r0 - 2 + i;
        bool yok = (unsigned)y < 128u;
        int ac = x - 2;
        bool cok = (unsigned)ac < 128u;
        raw1[i][x] = (yok && cok) ? p1[y * 128 + ac] : 0.f;
        raw2[i][x] = (yok && cok) ? p2[y * 128 + ac] : 0.f;
        if (x < 4) {
            int ac2 = 126 + x;
            bool c2ok = ac2 < 128;
            raw1[i][128 + x] = (yok && c2ok) ? p1[y * 128 + ac2] : 0.f;
            raw2[i][128 + x] = (yok && c2ok) ? p2[y * 128 + ac2] : 0.f;
        }
    }
    __syncthreads();

    const float* kd1 = dw_w + (size_t)c * 9;
    const float* kd2 = dw_w + (size_t)(340 + c) * 9;
    float d10 = kd1[0], d11 = kd1[1], d12 = kd1[2], d13 = kd1[3], d14 = kd1[4],
          d15 = kd1[5], d16 = kd1[6], d17 = kd1[7], d18 = kd1[8];
    float e10 = kd2[0], e11 = kd2[1], e12 = kd2[2], e13 = kd2[3], e14 = kd2[4],
          e15 = kd2[5], e16 = kd2[6], e17 = kd2[7], e18 = kd2[8];

    {
        int j = x + 1;
        #pragma unroll
        for (int i = 0; i < 10; i++) {
            int yv = r0 - 1 + i;
            bool yok = (unsigned)yv < 128u;
            float v1 = 0.f, v2 = 0.f;
            if (yok) {
                v1 = d10 * raw1[i][j]     + d11 * raw1[i][j + 1]     + d12 * raw1[i][j + 2]
                   + d13 * raw1[i + 1][j] + d14 * raw1[i + 1][j + 1] + d15 * raw1[i + 1][j + 2]
                   + d16 * raw1[i + 2][j] + d17 * raw1[i + 2][j + 1] + d18 * raw1[i + 2][j + 2];
                v2 = e10 * raw2[i][j]     + e11 * raw2[i][j + 1]     + e12 * raw2[i][j + 2]
                   + e13 * raw2[i + 1][j] + e14 * raw2[i + 1][j + 1] + e15 * raw2[i + 1][j + 2]
                   + e16 * raw2[i + 2][j] + e17 * raw2[i + 2][j + 1] + e18 * raw2[i + 2][j + 2];
            }
            t1[i][j] = v1;
            t2[i][j] = v2;
        }
        if (x < 10) { t1[x][0] = 0.f; t1[x][129] = 0.f; t2[x][0] = 0.f; t2[x][129] = 0.f; }
    }
    __syncthreads();

    const float* k1 = w1 + (size_t)c * 9;
    const float* k2 = w2 + (size_t)c * 9;
    float u00 = k1[0], u01 = k1[1], u02 = k1[2], u10 = k1[3], u11 = k1[4],
          u12 = k1[5], u20 = k1[6], u21 = k1[7], u22 = k1[8];
    float v00 = k2[0], v01 = k2[1], v02 = k2[2], v10 = k2[3], v11 = k2[4],
          v12 = k2[5], v20 = k2[6], v21 = k2[7], v22 = k2[8];

    float* op = g_scratch + OFF_X12 + ((size_t)b * 340 + c) * NP;
    #pragma unroll
    for (int i = 0; i < 8; i++) {
        float acc1 = u00 * t1[i][x]     + u01 * t1[i][x + 1]     + u02 * t1[i][x + 2]
                   + u10 * t1[i + 1][x] + u11 * t1[i + 1][x + 1] + u12 * t1[i + 1][x + 2]
                   + u20 * t1[i + 2][x] + u21 * t1[i + 2][x + 1] + u22 * t1[i + 2][x + 2];
        float acc2 = v00 * t2[i][x]     + v01 * t2[i][x + 1]     + v02 * t2[i][x + 2]
                   + v10 * t2[i + 1][x] + v11 * t2[i + 1][x + 1] + v12 * t2[i + 1][x + 2]
                   + v20 * t2[i + 2][x] + v21 * t2[i + 2][x + 1] + v22 * t2[i + 2][x + 2];
        float r1 = tanhf(acc1) + t1[i + 1][x + 1];
        float r2 = tanhf(acc2) + t2[i + 1][x + 1];
        op[(r0 + i) * 128 + x] = r1 * r2;
    }
}

// ============================================================================
extern "C" void kernel_launch(void* const* d_in, const int* in_sizes, int n_in,
                              void* d_out, int out_size)
{
    const float* x      = (const float*)d_in[0];
    const float* y      = (const float*)d_in[1];
    const float* ln_w   = (const float*)d_in[2];
    const float* ln_b   = (const float*)d_in[3];
    const float* temp   = (const float*)d_in[4];
    const float* q_w    = (const float*)d_in[5];
    const float* qdw_w  = (const float*)d_in[6];
    const float* kv_w   = (const float*)d_in[7];
    const float* kvdw_w = (const float*)d_in[8];
    const float* po_w   = (const float*)d_in[9];
    const float* g1_w   = (const float*)d_in[10];
    const float* g1_b   = (const float*)d_in[11];
    const float* g2_w   = (const float*)d_in[12];
    const float* g2_b   = (const float*)d_in[13];
    const float* pin_w  = (const float*)d_in[14];
    const float* dw_w   = (const float*)d_in[15];
    const float* dw1_w  = (const float*)d_in[16];
    const float* dw2_w  = (const float*)d_in[17];
    const float* pout_w = (const float*)d_in[18];
    float* out = (float*)d_out;

    static int smem_set = 0;
    if (!smem_set) {
        cudaFuncSetAttribute(gemm_pb, cudaFuncAttributeMaxDynamicSharedMemorySize,
                             PB_SMEM_BYTES);
        smem_set = 1;
    }

    dim3 lnGrid(NP / 256, BB);
    ln_kernel<<<lnGrid, 256>>>(x, 0, OFF_XN, ln_w, ln_b);
    ln_kernel<<<lnGrid, 256>>>(y, 0, OFF_YN, ln_w, ln_b);

    // SCAB branch (persistent-B tf32 GEMMs, K=128)
    dim3 gpb(NP / 128, 1, BB);
    gemm_pb<<<gpb, 256, PB_SMEM_BYTES>>>(q_w, 0, 0, OFF_XN, 128, nullptr, OFF_B1, 128,
                                         nullptr, 0, 0, 0, nullptr, nullptr, 0);
    dwconv_tiled<<<dim3(BB * 128, 8), 128>>>(OFF_B1, OFF_Q, qdw_w, 128, OFF_SSQP_Q);

    gemm_pb<<<gpb, 256, PB_SMEM_BYTES>>>(kv_w, 0, 0, OFF_YN, 128, nullptr, OFF_KVP, 256,
                                         nullptr, 0, 0, 0, nullptr, nullptr, 0);
    dwconv_tiled<<<dim3(BB * 256, 8), 128>>>(OFF_KVP, OFF_KV, kvdw_w, 256, OFF_SSQP_KV);

    ssq_reduce<<<2, 256>>>(OFF_SSQP_Q,  OFF_QSS, 128);
    ssq_reduce<<<2, 256>>>(OFF_SSQP_KV, OFF_KSS, 256);

    // gate -> dk (fused, fp32, proper M=64 tile)
    gate_fused<<<dim3(NP / 128, BB), 256>>>(g1_w, g1_b, g2_w, g2_b);
    finish_gate<<<1, 256>>>();

    // attention logits (fp32 — ordering-sensitive top-k)
    qk_partial<<<dim3(64, 8, BB), 256>>>();
    qk_reduce<<<dim3(8, BB), 256>>>(temp);
    mask_softmax<<<2, 256>>>();

    // fold attn into po: W_eff[b] = po_w @ blockdiag(attn_b);
    // xatt = x + W_eff @ v, with ln(xatt) fused into the epilogue -> YN
    compose_weff<<<BB, 128>>>(po_w);
    gemm_pb<<<gpb, 256, PB_SMEM_BYTES>>>(nullptr, OFF_WEFF, 16384,
                                         OFF_KV + (size_t)128 * NP, 256,
                                         nullptr, OFF_XATT, 128, x, 0, 1,
                                         1, ln_w, ln_b, OFF_YN);

    // IEL branch (persistent-B: B read once despite M=680 -> 6 m-tiles)
    gemm_pb<<<gpb, 256, PB_SMEM_BYTES>>>(pin_w, 0, 0, OFF_YN, 128, nullptr, OFF_TPRE, 680,
                                         nullptr, 0, 0, 0, nullptr, nullptr, 0);
    iel_fused<<<dim3(BB * 340, 16), 128>>>(dw_w, dw1_w, dw2_w);

    // final: out = conv1x1(x12, pout_w) + xatt  (K=340 -> streaming GEMM)
    dim3 gg128(NP / 128, 1, BB);
    gemm_tf32<<<gg128, 256>>>(pout_w, 0, 0, OFF_X12, 340, out, 0, 128, 340,
                              nullptr, OFF_XATT, 2);
}

// round 14
// speedup vs baseline: 1.1520x; 1.1520x over previous
#include <cuda_runtime.h>
#include <cuda_fp16.h>
#include <math.h>

#define NP 16384
#define BB 4

static constexpr size_t F1 = (size_t)BB * 128 * NP;  // 8,388,608 floats

static constexpr size_t OFF_XN   = 0;
static constexpr size_t OFF_YN   = F1;        // reused for z = ln(xatt) later
static constexpr size_t OFF_B1   = 2 * F1;    // q pre-dw
static constexpr size_t OFF_Q    = 3 * F1;
static constexpr size_t OFF_KVP  = 4 * F1;    // 2*F1
static constexpr size_t OFF_KV   = 6 * F1;    // 2*F1
static constexpr size_t OFF_WEFF = 8 * F1;    // per-batch composed po@attn weights
static constexpr size_t OFF_XATT = 9 * F1;
static constexpr size_t OFF_TPRE = 10 * F1;                       // 680ch
static constexpr size_t OFF_T    = OFF_TPRE + (size_t)BB*680*NP;
static constexpr size_t OFF_X12  = OFF_T    + (size_t)BB*680*NP;  // 340ch
static constexpr size_t OFF_ATTN = OFF_X12  + (size_t)BB*340*NP;  // 4*8*16*16
static constexpr size_t OFF_QSS  = OFF_ATTN + 8192;               // 512
static constexpr size_t OFF_KSS  = OFF_QSS  + 512;                // 512
static constexpr size_t OFF_PART = OFF_KSS  + 512;                // 512 gate partials
static constexpr size_t OFF_QKP  = OFF_PART + 512;                // 32*64*256 qk partials
static constexpr size_t OFF_SSQP_Q  = OFF_QKP + (size_t)32 * 64 * 256;  // 512*8
static constexpr size_t OFF_SSQP_KV = OFF_SSQP_Q + 4096;                // 1024*8
static constexpr size_t SCRATCH_TOTAL = OFF_SSQP_KV + 8192;

__device__ float g_scratch[SCRATCH_TOTAL];
__device__ int   g_dk;

// fp16 fragment-order smem sizes
// A chunk (128m x 32k): 16 frags x (32 lanes x 4 regs + 4 pad) = 16*132 u32
// B panel (128k x 128n): 8 kblk x 16 nblk x (32 lanes x 2 regs + 2 pad) = 8*16*66 u32
static constexpr int PB_ASF_U32 = 16 * 132;          // 2112
static constexpr int PB_BSF_U32 = 8 * 16 * 66;       // 8448
static constexpr int PB_SMEM_BYTES = (PB_ASF_U32 + PB_BSF_U32) * 4 + 8 * 32 * 8;  // 44288

__device__ __forceinline__ unsigned pack2h(float a, float b) {
    __half2 h = __floats2half2_rn(a, b);
    return *reinterpret_cast<unsigned*>(&h);
}

// ---------------- LayerNorm over channel axis (C=128), NCHW ----------------
__global__ void ln_kernel(const float* __restrict__ in_ptr, size_t in_off, size_t out_off,
                          const float* __restrict__ w, const float* __restrict__ bp)
{
    int p = blockIdx.x * blockDim.x + threadIdx.x;   // pixel within batch
    int b = blockIdx.y;
    const float* ip = (in_ptr ? in_ptr : g_scratch + in_off) + (size_t)b * 128 * NP + p;
    float s = 0.f, ss = 0.f;
    #pragma unroll 8
    for (int c = 0; c < 128; c++) { float v = ip[(size_t)c * NP]; s += v; ss += v * v; }
    float mu  = s * (1.f / 128.f);
    float var = ss * (1.f / 128.f) - mu * mu;
    float inv = rsqrtf(var + 1e-6f);
    float* op = g_scratch + out_off + (size_t)b * 128 * NP + p;
    #pragma unroll 8
    for (int c = 0; c < 128; c++) {
        float v = ip[(size_t)c * NP];
        op[(size_t)c * NP] = w[c] * ((v - mu) * inv) + bp[c];
    }
}

// ---------------- persistent-B fp16 GEMM (K=128 fixed) ------------------------
// B panel loaded ONCE (fp16 fragment order); m-tiles looped inside the CTA.
// rflag: 0 none, 1 residual from resid_ptr, 2 residual from scratch+resid_off
// lnflag: 1 -> (po path, M=128) also write YN = LayerNorm(out) to yn_off.
__global__ __launch_bounds__(256, 2)
void gemm_pb(const float* __restrict__ Wp, size_t w_off, size_t wstride,
             size_t in_off, int in_cs,
             float* __restrict__ out_ptr, size_t out_off,
             int M,
             const float* __restrict__ resid_ptr, size_t resid_off, int rflag,
             int lnflag, const float* __restrict__ lnw, const float* __restrict__ lnb,
             size_t yn_off)
{
    extern __shared__ unsigned smem_u[];
    unsigned* AsF = smem_u;
    unsigned* BsF = smem_u + PB_ASF_U32;
    float2* lnS = (float2*)(smem_u + PB_ASF_U32 + PB_BSF_U32);

    constexpr int K = 128;
    int b = blockIdx.z;
    const float* W = (Wp ? Wp : (const float*)(g_scratch + w_off)) + (size_t)b * wstride;
    const float* in = g_scratch + in_off + (size_t)b * in_cs * NP;
    float* out = (out_ptr ? out_ptr : g_scratch + out_off) + (size_t)b * M * NP;
    const float* res = nullptr;
    if (rflag == 1)      res = resid_ptr + (size_t)b * M * NP;
    else if (rflag == 2) res = g_scratch + resid_off + (size_t)b * M * NP;

    int n0 = blockIdx.x * 128;
    int t = threadIdx.x;
    int lane = t & 31, wid = t >> 5;
    int wm = (wid & 1) * 64;        // warp m offset in tile
    int wn = (wid >> 1) * 32;       // warp n offset in tile
    int gid = lane >> 2, tig = lane & 3;

    // ---- load FULL B panel (128k x 128n) as fp16 fragments, once ----
    #pragma unroll
    for (int i = 0; i < 8; i++) {
        int p = t + i * 256;                 // 0..2047
        int kp = p >> 5, nq = p & 31;        // kp: k-pair 0..63
        const float* r0 = &in[(size_t)(kp * 2) * NP + n0 + nq * 4];
        float4 va = *(const float4*)r0;
        float4 vb = *(const float4*)(r0 + NP);
        int blk = (kp >> 3) * 16 + (nq >> 1);
        int reg = (kp >> 2) & 1;
        unsigned* dst = &BsF[blk * 66 + (nq & 1) * 32 + (kp & 3) * 2 + reg];
        dst[0]  = pack2h(va.x, vb.x);
        dst[8]  = pack2h(va.y, vb.y);
        dst[16] = pack2h(va.z, vb.z);
        dst[24] = pack2h(va.w, vb.w);
    }
    // (first __syncthreads below covers these stores)

    int MT = (M + 127) >> 7;
    for (int mt = 0; mt < MT; mt++) {
        int m0 = mt << 7;
        float acc[4][4][4];
        #pragma unroll
        for (int i = 0; i < 4; i++)
            #pragma unroll
            for (int j = 0; j < 4; j++)
                #pragma unroll
                for (int r = 0; r < 4; r++) acc[i][j][r] = 0.f;

        for (int kt = 0; kt < 4; kt++) {
            int k0 = kt << 5;
            // ---- A chunk (128m x 32k) fp16 fragments ----
            #pragma unroll
            for (int i = 0; i < 4; i++) {
                int lin = t + i * 256;            // 0..1023
                int m = lin >> 3, kq = lin & 7;   // kq: 4-k quad
                int gm = m0 + m, gk = k0 + kq * 4;
                float v0 = 0.f, v1 = 0.f, v2 = 0.f, v3 = 0.f;
                if (gm < M) {
                    float4 w4 = *(const float4*)&W[(size_t)gm * K + gk];
                    v0 = w4.x; v1 = w4.y; v2 = w4.z; v3 = w4.w;
                }
                int fb = (kq >> 2) * 8 + (m >> 4);
                int reg = ((m & 15) >> 3) + (((kq >> 1) & 1) << 1);
                int lanew = (m & 7) * 4 + ((kq & 1) << 1);
                unsigned* dst = &AsF[fb * 132 + lanew * 4 + reg];
                dst[0] = pack2h(v0, v1);
                dst[4] = pack2h(v2, v3);
            }
            __syncthreads();

            #pragma unroll
            for (int ks = 0; ks < 2; ks++) {
                int kbg = kt * 2 + ks;            // global 16-k block 0..7
                unsigned af[4][4], bf[4][2];
                #pragma unroll
                for (int mi = 0; mi < 4; mi++) {
                    int fb = ks * 8 + (wm >> 4) + mi;
                    uint4 av = *(const uint4*)&AsF[fb * 132 + lane * 4];
                    af[mi][0] = av.x; af[mi][1] = av.y; af[mi][2] = av.z; af[mi][3] = av.w;
                }
                #pragma unroll
                for (int ni = 0; ni < 4; ni++) {
                    int blk = kbg * 16 + (wn >> 3) + ni;
                    uint2 bv = *(const uint2*)&BsF[blk * 66 + lane * 2];
                    bf[ni][0] = bv.x; bf[ni][1] = bv.y;
                }
                #pragma unroll
                for (int mi = 0; mi < 4; mi++)
                    #pragma unroll
                    for (int ni = 0; ni < 4; ni++) {
                        asm volatile(
                            "mma.sync.aligned.m16n8k16.row.col.f32.f16.f16.f32 "
                            "{%0,%1,%2,%3}, {%4,%5,%6,%7}, {%8,%9}, {%0,%1,%2,%3};"
                            : "+f"(acc[mi][ni][0]), "+f"(acc[mi][ni][1]),
                              "+f"(acc[mi][ni][2]), "+f"(acc[mi][ni][3])
                            : "r"(af[mi][0]), "r"(af[mi][1]), "r"(af[mi][2]), "r"(af[mi][3]),
                              "r"(bf[ni][0]), "r"(bf[ni][1]));
                    }
            }
            __syncthreads();
        }

        if (!lnflag) {
            #pragma unroll
            for (int mi = 0; mi < 4; mi++) {
                int row0 = m0 + wm + mi * 16 + gid;
                int row1 = row0 + 8;
                #pragma unroll
                for (int ni = 0; ni < 4; ni++) {
                    int col = n0 + wn + ni * 8 + tig * 2;
                    if (row0 < M) {
                        float2 v = make_float2(acc[mi][ni][0], acc[mi][ni][1]);
                        if (res) {
                            float2 r = *(const float2*)&res[(size_t)row0 * NP + col];
                            v.x += r.x; v.y += r.y;
                        }
                        *(float2*)&out[(size_t)row0 * NP + col] = v;
                    }
                    if (row1 < M) {
                        float2 v = make_float2(acc[mi][ni][2], acc[mi][ni][3]);
                        if (res) {
                            float2 r = *(const float2*)&res[(size_t)row1 * NP + col];
                            v.x += r.x; v.y += r.y;
                        }
                        *(float2*)&out[(size_t)row1 * NP + col] = v;
                    }
                }
            }
        } else {
            // ---- po epilogue: write xatt AND yn = LayerNorm(xatt). M=128, m0=0. ----
            float* ynp = g_scratch + yn_off + (size_t)b * 128 * NP;
            float s[4][2], q2[4][2];
            #pragma unroll
            for (int ni = 0; ni < 4; ni++) { s[ni][0] = s[ni][1] = 0.f; q2[ni][0] = q2[ni][1] = 0.f; }

            #pragma unroll
            for (int mi = 0; mi < 4; mi++) {
                int row0 = wm + mi * 16 + gid;
                int row1 = row0 + 8;
                #pragma unroll
                for (int ni = 0; ni < 4; ni++) {
                    int col = n0 + wn + ni * 8 + tig * 2;
                    float2 r0v = *(const float2*)&res[(size_t)row0 * NP + col];
                    float2 r1v = *(const float2*)&res[(size_t)row1 * NP + col];
                    acc[mi][ni][0] += r0v.x; acc[mi][ni][1] += r0v.y;
                    acc[mi][ni][2] += r1v.x; acc[mi][ni][3] += r1v.y;
                    *(float2*)&out[(size_t)row0 * NP + col] = make_float2(acc[mi][ni][0], acc[mi][ni][1]);
                    *(float2*)&out[(size_t)row1 * NP + col] = make_float2(acc[mi][ni][2], acc[mi][ni][3]);
                    s[ni][0]  += acc[mi][ni][0] + acc[mi][ni][2];
                    s[ni][1]  += acc[mi][ni][1] + acc[mi][ni][3];
                    q2[ni][0] += acc[mi][ni][0] * acc[mi][ni][0] + acc[mi][ni][2] * acc[mi][ni][2];
                    q2[ni][1] += acc[mi][ni][1] * acc[mi][ni][1] + acc[mi][ni][3] * acc[mi][ni][3];
                }
            }
            #pragma unroll
            for (int mask = 4; mask <= 16; mask <<= 1) {
                #pragma unroll
                for (int ni = 0; ni < 4; ni++) {
                    s[ni][0]  += __shfl_xor_sync(0xffffffffu, s[ni][0],  mask);
                    s[ni][1]  += __shfl_xor_sync(0xffffffffu, s[ni][1],  mask);
                    q2[ni][0] += __shfl_xor_sync(0xffffffffu, q2[ni][0], mask);
                    q2[ni][1] += __shfl_xor_sync(0xffffffffu, q2[ni][1], mask);
                }
            }
            if (gid == 0) {
                #pragma unroll
                for (int ni = 0; ni < 4; ni++) {
                    lnS[wid * 32 + ni * 8 + tig * 2 + 0] = make_float2(s[ni][0], q2[ni][0]);
                    lnS[wid * 32 + ni * 8 + tig * 2 + 1] = make_float2(s[ni][1], q2[ni][1]);
                }
            }
            __syncthreads();
            float mu[4][2], inv[4][2];
            #pragma unroll
            for (int ni = 0; ni < 4; ni++) {
                #pragma unroll
                for (int c = 0; c < 2; c++) {
                    float2 other = lnS[(wid ^ 1) * 32 + ni * 8 + tig * 2 + c];
                    float ts = s[ni][c] + other.x;
                    float tq = q2[ni][c] + other.y;
                    float m_ = ts * (1.f / 128.f);
                    float var = tq * (1.f / 128.f) - m_ * m_;
                    mu[ni][c] = m_;
                    inv[ni][c] = rsqrtf(var + 1e-6f);
                }
            }
            #pragma unroll
            for (int mi = 0; mi < 4; mi++) {
                int row0 = wm + mi * 16 + gid;
                int row1 = row0 + 8;
                float lw0 = lnw[row0], lb0 = lnb[row0];
                float lw1 = lnw[row1], lb1 = lnb[row1];
                #pragma unroll
                for (int ni = 0; ni < 4; ni++) {
                    int col = n0 + wn + ni * 8 + tig * 2;
                    float y00 = lw0 * ((acc[mi][ni][0] - mu[ni][0]) * inv[ni][0]) + lb0;
                    float y01 = lw0 * ((acc[mi][ni][1] - mu[ni][1]) * inv[ni][1]) + lb0;
                    float y10 = lw1 * ((acc[mi][ni][2] - mu[ni][0]) * inv[ni][0]) + lb1;
                    float y11 = lw1 * ((acc[mi][ni][3] - mu[ni][1]) * inv[ni][1]) + lb1;
                    *(float2*)&ynp[(size_t)row0 * NP + col] = make_float2(y00, y01);
                    *(float2*)&ynp[(size_t)row1 * NP + col] = make_float2(y10, y11);
                }
            }
        }
    }
}

// ---------------- streaming fp16 GEMM (pout path, K=340) ---------------------
__global__ __launch_bounds__(256, 2)
void gemm_hstream(const float* __restrict__ Wp, size_t in_off, int in_cs,
                  float* __restrict__ out_ptr,
                  int M, int K, size_t resid_off)
{
    __shared__ unsigned AsF[16 * 132];
    __shared__ unsigned BsF[2 * 16 * 66];

    int b = blockIdx.z;
    const float* W = Wp;
    const float* in = g_scratch + in_off + (size_t)b * in_cs * NP;
    float* out = out_ptr + (size_t)b * M * NP;
    const float* res = g_scratch + resid_off + (size_t)b * M * NP;

    int m0 = blockIdx.y * 128, n0 = blockIdx.x * 128;
    int t = threadIdx.x;
    int lane = t & 31, wid = t >> 5;
    int wm = (wid & 1) * 64;
    int wn = (wid >> 1) * 32;
    int gid = lane >> 2, tig = lane & 3;

    float acc[4][4][4];
    #pragma unroll
    for (int i = 0; i < 4; i++)
        #pragma unroll
        for (int j = 0; j < 4; j++)
            #pragma unroll
            for (int r = 0; r < 4; r++) acc[i][j][r] = 0.f;

    int KT = (K + 31) >> 5;
    float4 va[2], vb[2];
    #pragma unroll
    for (int i = 0; i < 2; i++) {
        int p = t + i * 256;
        int kp = p >> 5, nq = p & 31;
        int k = kp * 2;
        va[i] = (k < K)     ? *(const float4*)&in[(size_t)k * NP + n0 + nq * 4]
                            : make_float4(0.f, 0.f, 0.f, 0.f);
        vb[i] = (k + 1 < K) ? *(const float4*)&in[(size_t)(k + 1) * NP + n0 + nq * 4]
                            : make_float4(0.f, 0.f, 0.f, 0.f);
    }

    for (int kt = 0; kt < KT; kt++) {
        int k0 = kt << 5;
        // ---- A chunk fp16 fragments ----
        #pragma unroll
        for (int i = 0; i < 4; i++) {
            int lin = t + i * 256;
            int m = lin >> 3, kq = lin & 7;
            int gm = m0 + m, gk = k0 + kq * 4;
            float v0 = 0.f, v1 = 0.f, v2 = 0.f, v3 = 0.f;
            if (gm < M) {
                if (gk + 3 < K) {
                    float4 w4 = *(const float4*)&W[(size_t)gm * K + gk];
                    v0 = w4.x; v1 = w4.y; v2 = w4.z; v3 = w4.w;
                } else {
                    if (gk + 0 < K) v0 = W[(size_t)gm * K + gk + 0];
                    if (gk + 1 < K) v1 = W[(size_t)gm * K + gk + 1];
                    if (gk + 2 < K) v2 = W[(size_t)gm * K + gk + 2];
                    if (gk + 3 < K) v3 = W[(size_t)gm * K + gk + 3];
                }
            }
            int fb = (kq >> 2) * 8 + (m >> 4);
            int reg = ((m & 15) >> 3) + (((kq >> 1) & 1) << 1);
            int lanew = (m & 7) * 4 + ((kq & 1) << 1);
            unsigned* dst = &AsF[fb * 132 + lanew * 4 + reg];
            dst[0] = pack2h(v0, v1);
            dst[4] = pack2h(v2, v3);
        }
        // ---- B chunk STS from prefetched registers ----
        #pragma unroll
        for (int i = 0; i < 2; i++) {
            int p = t + i * 256;
            int kp = p >> 5, nq = p & 31;
            int blk = (kp >> 3) * 16 + (nq >> 1);
            int reg = (kp >> 2) & 1;
            unsigned* dst = &BsF[blk * 66 + (nq & 1) * 32 + (kp & 3) * 2 + reg];
            dst[0]  = pack2h(va[i].x, vb[i].x);
            dst[8]  = pack2h(va[i].y, vb[i].y);
            dst[16] = pack2h(va[i].z, vb[i].z);
            dst[24] = pack2h(va[i].w, vb[i].w);
        }
        __syncthreads();

        if (kt + 1 < KT) {
            int kn0 = (kt + 1) << 5;
            #pragma unroll
            for (int i = 0; i < 2; i++) {
                int p = t + i * 256;
                int kp = p >> 5, nq = p & 31;
                int k = kn0 + kp * 2;
                va[i] = (k < K)     ? *(const float4*)&in[(size_t)k * NP + n0 + nq * 4]
                                    : make_float4(0.f, 0.f, 0.f, 0.f);
                vb[i] = (k + 1 < K) ? *(const float4*)&in[(size_t)(k + 1) * NP + n0 + nq * 4]
                                    : make_float4(0.f, 0.f, 0.f, 0.f);
            }
        }

        #pragma unroll
        for (int ks = 0; ks < 2; ks++) {
            unsigned af[4][4], bf[4][2];
            #pragma unroll
            for (int mi = 0; mi < 4; mi++) {
                int fb = ks * 8 + (wm >> 4) + mi;
                uint4 av = *(const uint4*)&AsF[fb * 132 + lane * 4];
                af[mi][0] = av.x; af[mi][1] = av.y; af[mi][2] = av.z; af[mi][3] = av.w;
            }
            #pragma unroll
            for (int ni = 0; ni < 4; ni++) {
                int blk = ks * 16 + (wn >> 3) + ni;
                uint2 bv = *(const uint2*)&BsF[blk * 66 + lane * 2];
                bf[ni][0] = bv.x; bf[ni][1] = bv.y;
            }
            #pragma unroll
            for (int mi = 0; mi < 4; mi++)
                #pragma unroll
                for (int ni = 0; ni < 4; ni++) {
                    asm volatile(
                        "mma.sync.aligned.m16n8k16.row.col.f32.f16.f16.f32 "
                        "{%0,%1,%2,%3}, {%4,%5,%6,%7}, {%8,%9}, {%0,%1,%2,%3};"
                        : "+f"(acc[mi][ni][0]), "+f"(acc[mi][ni][1]),
                          "+f"(acc[mi][ni][2]), "+f"(acc[mi][ni][3])
                        : "r"(af[mi][0]), "r"(af[mi][1]), "r"(af[mi][2]), "r"(af[mi][3]),
                          "r"(bf[ni][0]), "r"(bf[ni][1]));
                }
        }
        __syncthreads();
    }

    #pragma unroll
    for (int mi = 0; mi < 4; mi++) {
        int row0 = m0 + wm + mi * 16 + gid;
        int row1 = row0 + 8;
        #pragma unroll
        for (int ni = 0; ni < 4; ni++) {
            int col = n0 + wn + ni * 8 + tig * 2;
            if (row0 < M) {
                float2 r = *(const float2*)&res[(size_t)row0 * NP + col];
                *(float2*)&out[(size_t)row0 * NP + col] =
                    make_float2(acc[mi][ni][0] + r.x, acc[mi][ni][1] + r.y);
            }
            if (row1 < M) {
                float2 r = *(const float2*)&res[(size_t)row1 * NP + col];
                *(float2*)&out[(size_t)row1 * NP + col] =
                    make_float2(acc[mi][ni][2] + r.x, acc[mi][ni][3] + r.y);
            }
        }
    }
}

// ---------------- fused gate: g1 GEMM (M=64) + g2 + sigmoid + partials --------
__global__ __launch_bounds__(256, 2)
void gate_fused(const float* __restrict__ W, const float* __restrict__ g1b,
                const float* __restrict__ g2w, const float* __restrict__ g2b)
{
    __shared__ float As[16][68];     // [k][m], 64 rows
    __shared__ float Bs[16][132];    // [k][n], 128 pixels
    __shared__ float sred[16][136];  // per-ty partials per pixel
    __shared__ float red[128];

    int b = blockIdx.y;
    int n0 = blockIdx.x * 128;
    const float* in = g_scratch + OFF_XN + (size_t)b * 128 * NP;
    int t = threadIdx.x, tx = t & 15, ty = t >> 4;

    float acc[4][8];
    #pragma unroll
    for (int i = 0; i < 4; i++)
        #pragma unroll
        for (int j = 0; j < 8; j++) acc[i][j] = 0.f;

    for (int kt = 0; kt < 8; kt++) {
        int k0 = kt * 16;
        #pragma unroll
        for (int i = 0; i < 4; i++) {
            int lin = t * 4 + i;           // 0..1023
            int m = lin >> 4, kk = lin & 15;
            As[kk][m] = W[(size_t)m * 128 + k0 + kk];
        }
        #pragma unroll
        for (int i = 0; i < 2; i++) {
            int idx = t * 2 + i;           // 0..511
            int kk = idx >> 5, nq = idx & 31;
            float4 v4 = *(const float4*)&in[(size_t)(k0 + kk) * NP + n0 + nq * 4];
            Bs[kk][nq * 4 + 0] = v4.x;
            Bs[kk][nq * 4 + 1] = v4.y;
            Bs[kk][nq * 4 + 2] = v4.z;
            Bs[kk][nq * 4 + 3] = v4.w;
        }
        __syncthreads();
        #pragma unroll
        for (int kk = 0; kk < 16; kk++) {
            float a[4], bv[8];
            #pragma unroll
            for (int i = 0; i < 4; i++) a[i] = As[kk][ty * 4 + i];
            #pragma unroll
            for (int j = 0; j < 8; j++) bv[j] = Bs[kk][tx * 8 + j];
            #pragma unroll
            for (int i = 0; i < 4; i++)
                #pragma unroll
                for (int j = 0; j < 8; j++)
                    acc[i][j] += a[i] * bv[j];
        }
        __syncthreads();
    }

    float part[8];
    #pragma unroll
    for (int j = 0; j < 8; j++) part[j] = 0.f;
    #pragma unroll
    for (int i = 0; i < 4; i++) {
        int m = ty * 4 + i;
        float gb = g1b[m], gw = g2w[m];
        #pragma unroll
        for (int j = 0; j < 8; j++)
            part[j] += gw * fmaxf(acc[i][j] + gb, 0.f);
    }
    #pragma unroll
    for (int j = 0; j < 8; j++) sred[ty][tx * 8 + j] = part[j];
    __syncthreads();

    if (t < 128) {
        float s = g2b[0];
        #pragma unroll
        for (int r = 0; r < 16; r++) s += sred[r][t];
        red[t] = 1.f / (1.f + expf(-s));
    }
    __syncthreads();
    for (int st = 64; st; st >>= 1) {
        if (t < st) red[t] += red[t + st];
        __syncthreads();
    }
    if (!t) g_scratch[OFF_PART + (size_t)b * 128 + blockIdx.x] = red[0];
}

__global__ void finish_gate()
{
    __shared__ float red[256];
    int t = threadIdx.x;
    red[t] = g_scratch[OFF_PART + t] + g_scratch[OFF_PART + t + 256];
    __syncthreads();
    for (int st = 128; st; st >>= 1) {
        if (t < st) red[t] += red[t + st];
        __syncthreads();
    }
    if (!t) {
        float mean = red[0] * (1.f / 65536.f);
        int dk = (int)(16.f * mean);               // trunc like astype(int32)
        g_dk = dk < 1 ? 1 : (dk > 16 ? 16 : dk);
    }
}

// ---------------- tiled depthwise 3x3, pad=1, with sumsq partials ------------
__global__ void dwconv_tiled(size_t in_off, size_t out_off, const float* __restrict__ wts,
                             int C, size_t ssq_off)
{
    __shared__ float tile[18][130];
    __shared__ float red[128];
    int plane = blockIdx.x;                 // b*C + c
    int c = plane % C;
    int r0 = blockIdx.y * 16;
    int x = threadIdx.x;                    // 0..127
    const float* ip = g_scratch + in_off + (size_t)plane * NP;
    float* op = g_scratch + out_off + (size_t)plane * NP;

    #pragma unroll
    for (int i = 0; i < 18; i++) {
        int y = r0 - 1 + i;
        tile[i][x + 1] = ((unsigned)y < 128u) ? ip[y * 128 + x] : 0.f;
    }
    if (x < 18) { tile[x][0] = 0.f; tile[x][129] = 0.f; }
    __syncthreads();

    const float* kp = wts + c * 9;
    float w00 = kp[0], w01 = kp[1], w02 = kp[2];
    float w10 = kp[3], w11 = kp[4], w12 = kp[5];
    float w20 = kp[6], w21 = kp[7], w22 = kp[8];

    float a0 = tile[0][x], a1 = tile[0][x + 1], a2 = tile[0][x + 2];
    float b0 = tile[1][x], b1 = tile[1][x + 1], b2 = tile[1][x + 2];
    float ssq = 0.f;
    #pragma unroll
    for (int i = 0; i < 16; i++) {
        float c0 = tile[i + 2][x], c1 = tile[i + 2][x + 1], c2 = tile[i + 2][x + 2];
        float acc = w00 * a0 + w01 * a1 + w02 * a2
                  + w10 * b0 + w11 * b1 + w12 * b2
                  + w20 * c0 + w21 * c1 + w22 * c2;
        op[(r0 + i) * 128 + x] = acc;
        ssq += acc * acc;
        a0 = b0; a1 = b1; a2 = b2;
        b0 = c0; b1 = c1; b2 = c2;
    }
    red[x] = ssq; __syncthreads();
    for (int st = 64; st; st >>= 1) {
        if (x < st) red[x] += red[x + st];
        __syncthreads();
    }
    if (!x) g_scratch[ssq_off + (size_t)plane * 8 + blockIdx.y] = red[0];
}

// ---------------- reduce 8 sumsq partials per channel ----------------
__global__ void ssq_reduce(size_t part_off, size_t out_off, int in_cs)
{
    int idx = blockIdx.x * blockDim.x + threadIdx.x;   // 0..511
    if (idx >= 512) return;
    int b = idx >> 7, c = idx & 127;
    const float* p = g_scratch + part_off + ((size_t)b * in_cs + c) * 8;
    float s = 0.f;
    #pragma unroll
    for (int r = 0; r < 8; r++) s += p[r];
    g_scratch[out_off + idx] = s;
}

// ---------------- qk partials: 16x16 over a 256-px chunk per block ------------
__global__ void qk_partial()
{
    __shared__ float qs[16][257];
    __shared__ float ks[16][257];
    int chunk = blockIdx.x, h = blockIdx.y, b = blockIdx.z;
    int n0 = chunk * 256;
    int t = threadIdx.x;
    const float* qbase = g_scratch + OFF_Q  + ((size_t)b * 128 + h * 16) * NP + n0;
    const float* kbase = g_scratch + OFF_KV + ((size_t)b * 256 + h * 16) * NP + n0;
    #pragma unroll
    for (int r = 0; r < 16; r++) {
        qs[r][t] = qbase[(size_t)r * NP + t];
        ks[r][t] = kbase[(size_t)r * NP + t];
    }
    __syncthreads();
    int c = t >> 4, d = t & 15;
    float acc = 0.f;
    #pragma unroll 8
    for (int n = 0; n < 256; n++) acc += qs[c][n] * ks[d][n];
    g_scratch[OFF_QKP + (((size_t)(b * 8 + h) * 64 + chunk) * 256) + t] = acc;
}

// ---------------- qk reduce + normalize + temperature -------------------------
__global__ void qk_reduce(const float* __restrict__ temp)
{
    int h = blockIdx.x, b = blockIdx.y;
    int t = threadIdx.x;
    float acc = 0.f;
    const float* p = g_scratch + OFF_QKP + (size_t)(b * 8 + h) * 64 * 256 + t;
    #pragma unroll 8
    for (int j = 0; j < 64; j++) acc += p[j * 256];
    int c = t >> 4, d = t & 15;
    float qn = fmaxf(sqrtf(g_scratch[OFF_QSS + b * 128 + h * 16 + c]), 1e-12f);
    float kn = fmaxf(sqrtf(g_scratch[OFF_KSS + b * 128 + h * 16 + d]), 1e-12f);
    g_scratch[OFF_ATTN + (size_t)(b * 8 + h) * 256 + t] = acc / (qn * kn) * temp[h];
}

// ---------------- dynamic top-k mask + softmax --------------------------------
__global__ void mask_softmax()
{
    int r = blockIdx.x * blockDim.x + threadIdx.x;   // 512 rows total
    if (r >= BB * 8 * 16) return;
    float* row = g_scratch + OFF_ATTN + (size_t)r * 16;
    int dk = g_dk;
    float vals[16];
    #pragma unroll
    for (int i = 0; i < 16; i++) vals[i] = row[i];
    float mx = -3.4e38f;
    bool keep[16];
    #pragma unroll
    for (int i = 0; i < 16; i++) {
        int rank = 0;
        #pragma unroll
        for (int j = 0; j < 16; j++)
            rank += (vals[j] > vals[i]) || (vals[j] == vals[i] && j < i);
        keep[i] = rank < dk;
        if (keep[i] && vals[i] > mx) mx = vals[i];
    }
    float sum = 0.f, e[16];
    #pragma unroll
    for (int i = 0; i < 16; i++) { e[i] = keep[i] ? expf(vals[i] - mx) : 0.f; sum += e[i]; }
    float isum = 1.f / sum;
    #pragma unroll
    for (int i = 0; i < 16; i++) row[i] = e[i] * isum;
}

// ---------------- W_eff[b] = po_w @ blockdiag(attn_b) ------------------------
__global__ void compose_weff(const float* __restrict__ po_w)
{
    __shared__ float at[2048];
    int b = blockIdx.x;
    int t = threadIdx.x;
    for (int i = t; i < 2048; i += 128) at[i] = g_scratch[OFF_ATTN + (size_t)b * 2048 + i];
    __syncthreads();
    int m = t;
    float* wo = g_scratch + OFF_WEFF + ((size_t)b * 128 + m) * 128;
    #pragma unroll
    for (int h = 0; h < 8; h++) {
        float pw[16];
        #pragma unroll
        for (int c = 0; c < 16; c++) pw[c] = po_w[(size_t)m * 128 + h * 16 + c];
        #pragma unroll
        for (int d = 0; d < 16; d++) {
            float acc = 0.f;
            #pragma unroll
            for (int c = 0; c < 16; c++) acc += pw[c] * at[h * 256 + c * 16 + d];
            wo[h * 16 + d] = acc;
        }
    }
}

// ---------------- fully fused IEL tail (8-row strips) -------------------------
__global__ void iel_fused(const float* __restrict__ dw_w,
                          const float* __restrict__ w1, const float* __restrict__ w2)
{
    __shared__ float raw1[12][132], raw2[12][132];
    __shared__ float t1[10][130], t2[10][130];
    int pid = blockIdx.x;                  // b*340 + c
    int b = pid / 340, c = pid % 340;
    int r0 = blockIdx.y * 8;
    int x = threadIdx.x;                   // 0..127
    const float* p1 = g_scratch + OFF_TPRE + ((size_t)b * 680 + c) * NP;
    const float* p2 = p1 + (size_t)340 * NP;

    #pragma unroll
    for (int i = 0; i < 12; i++) {
        int y = r0 - 2 + i;
        bool yok = (unsigned)y < 128u;
        int ac = x - 2;
        bool cok = (unsigned)ac < 128u;
        raw1[i][x] = (yok && cok) ? p1[y * 128 + ac] : 0.f;
        raw2[i][x] = (yok && cok) ? p2[y * 128 + ac] : 0.f;
        if (x < 4) {
            int ac2 = 126 + x;
            bool c2ok = ac2 < 128;
            raw1[i][128 + x] = (yok && c2ok) ? p1[y * 128 + ac2] : 0.f;
            raw2[i][128 + x] = (yok && c2ok) ? p2[y * 128 + ac2] : 0.f;
        }
    }
    __syncthreads();

    const float* kd1 = dw_w + (size_t)c * 9;
    const float* kd2 = dw_w + (size_t)(340 + c) * 9;
    float d10 = kd1[0], d11 = kd1[1], d12 = kd1[2], d13 = kd1[3], d14 = kd1[4],
          d15 = kd1[5], d16 = kd1[6], d17 = kd1[7], d18 = kd1[8];
    float e10 = kd2[0], e11 = kd2[1], e12 = kd2[2], e13 = kd2[3], e14 = kd2[4],
          e15 = kd2[5], e16 = kd2[6], e17 = kd2[7], e18 = kd2[8];

    {
        int j = x + 1;
        #pragma unroll
        for (int i = 0; i < 10; i++) {
            int yv = r0 - 1 + i;
            bool yok = (unsigned)yv < 128u;
            float v1 = 0.f, v2 = 0.f;
            if (yok) {
                v1 = d10 * raw1[i][j]     + d11 * raw1[i][j + 1]     + d12 * raw1[i][j + 2]
                   + d13 * raw1[i + 1][j] + d14 * raw1[i + 1][j + 1] + d15 * raw1[i + 1][j + 2]
                   + d16 * raw1[i + 2][j] + d17 * raw1[i + 2][j + 1] + d18 * raw1[i + 2][j + 2];
                v2 = e10 * raw2[i][j]     + e11 * raw2[i][j + 1]     + e12 * raw2[i][j + 2]
                   + e13 * raw2[i + 1][j] + e14 * raw2[i + 1][j + 1] + e15 * raw2[i + 1][j + 2]
                   + e16 * raw2[i + 2][j] + e17 * raw2[i + 2][j + 1] + e18 * raw2[i + 2][j + 2];
            }
            t1[i][j] = v1;
            t2[i][j] = v2;
        }
        if (x < 10) { t1[x][0] = 0.f; t1[x][129] = 0.f; t2[x][0] = 0.f; t2[x][129] = 0.f; }
    }
    __syncthreads();

    const float* k1 = w1 + (size_t)c * 9;
    const float* k2 = w2 + (size_t)c * 9;
    float u00 = k1[0], u01 = k1[1], u02 = k1[2], u10 = k1[3], u11 = k1[4],
          u12 = k1[5], u20 = k1[6], u21 = k1[7], u22 = k1[8];
    float v00 = k2[0], v01 = k2[1], v02 = k2[2], v10 = k2[3], v11 = k2[4],
          v12 = k2[5], v20 = k2[6], v21 = k2[7], v22 = k2[8];

    float* op = g_scratch + OFF_X12 + ((size_t)b * 340 + c) * NP;
    #pragma unroll
    for (int i = 0; i < 8; i++) {
        float acc1 = u00 * t1[i][x]     + u01 * t1[i][x + 1]     + u02 * t1[i][x + 2]
                   + u10 * t1[i + 1][x] + u11 * t1[i + 1][x + 1] + u12 * t1[i + 1][x + 2]
                   + u20 * t1[i + 2][x] + u21 * t1[i + 2][x + 1] + u22 * t1[i + 2][x + 2];
        float acc2 = v00 * t2[i][x]     + v01 * t2[i][x + 1]     + v02 * t2[i][x + 2]
                   + v10 * t2[i + 1][x] + v11 * t2[i + 1][x + 1] + v12 * t2[i + 1][x + 2]
                   + v20 * t2[i + 2][x] + v21 * t2[i + 2][x + 1] + v22 * t2[i + 2][x + 2];
        float r1 = tanhf(acc1) + t1[i + 1][x + 1];
        float r2 = tanhf(acc2) + t2[i + 1][x + 1];
        op[(r0 + i) * 128 + x] = r1 * r2;
    }
}

// ============================================================================
extern "C" void kernel_launch(void* const* d_in, const int* in_sizes, int n_in,
                              void* d_out, int out_size)
{
    const float* x      = (const float*)d_in[0];
    const float* y      = (const float*)d_in[1];
    const float* ln_w   = (const float*)d_in[2];
    const float* ln_b   = (const float*)d_in[3];
    const float* temp   = (const float*)d_in[4];
    const float* q_w    = (const float*)d_in[5];
    const float* qdw_w  = (const float*)d_in[6];
    const float* kv_w   = (const float*)d_in[7];
    const float* kvdw_w = (const float*)d_in[8];
    const float* po_w   = (const float*)d_in[9];
    const float* g1_w   = (const float*)d_in[10];
    const float* g1_b   = (const float*)d_in[11];
    const float* g2_w   = (const float*)d_in[12];
    const float* g2_b   = (const float*)d_in[13];
    const float* pin_w  = (const float*)d_in[14];
    const float* dw_w   = (const float*)d_in[15];
    const float* dw1_w  = (const float*)d_in[16];
    const float* dw2_w  = (const float*)d_in[17];
    const float* pout_w = (const float*)d_in[18];
    float* out = (float*)d_out;

    static int smem_set = 0;
    if (!smem_set) {
        cudaFuncSetAttribute(gemm_pb, cudaFuncAttributeMaxDynamicSharedMemorySize,
                             PB_SMEM_BYTES);
        smem_set = 1;
    }

    dim3 lnGrid(NP / 256, BB);
    ln_kernel<<<lnGrid, 256>>>(x, 0, OFF_XN, ln_w, ln_b);
    ln_kernel<<<lnGrid, 256>>>(y, 0, OFF_YN, ln_w, ln_b);

    // SCAB branch (fp16 persistent-B GEMMs, K=128)
    dim3 gpb(NP / 128, 1, BB);
    gemm_pb<<<gpb, 256, PB_SMEM_BYTES>>>(q_w, 0, 0, OFF_XN, 128, nullptr, OFF_B1, 128,
                                         nullptr, 0, 0, 0, nullptr, nullptr, 0);
    dwconv_tiled<<<dim3(BB * 128, 8), 128>>>(OFF_B1, OFF_Q, qdw_w, 128, OFF_SSQP_Q);

    gemm_pb<<<gpb, 256, PB_SMEM_BYTES>>>(kv_w, 0, 0, OFF_YN, 128, nullptr, OFF_KVP, 256,
                                         nullptr, 0, 0, 0, nullptr, nullptr, 0);
    dwconv_tiled<<<dim3(BB * 256, 8), 128>>>(OFF_KVP, OFF_KV, kvdw_w, 256, OFF_SSQP_KV);

    ssq_reduce<<<2, 256>>>(OFF_SSQP_Q,  OFF_QSS, 128);
    ssq_reduce<<<2, 256>>>(OFF_SSQP_KV, OFF_KSS, 256);

    // gate -> dk (fused, fp32, bit-stable)
    gate_fused<<<dim3(NP / 128, BB), 256>>>(g1_w, g1_b, g2_w, g2_b);
    finish_gate<<<1, 256>>>();

    // attention logits (fp32 — ordering-sensitive top-k)
    qk_partial<<<dim3(64, 8, BB), 256>>>();
    qk_reduce<<<dim3(8, BB), 256>>>(temp);
    mask_softmax<<<2, 256>>>();

    // fold attn into po: W_eff[b] = po_w @ blockdiag(attn_b);
    // xatt = x + W_eff @ v, with ln(xatt) fused into the epilogue -> YN
    compose_weff<<<BB, 128>>>(po_w);
    gemm_pb<<<gpb, 256, PB_SMEM_BYTES>>>(nullptr, OFF_WEFF, 16384,
                                         OFF_KV + (size_t)128 * NP, 256,
                                         nullptr, OFF_XATT, 128, x, 0, 1,
                                         1, ln_w, ln_b, OFF_YN);

    // IEL branch (fp16 persistent-B, M=680)
    gemm_pb<<<gpb, 256, PB_SMEM_BYTES>>>(pin_w, 0, 0, OFF_YN, 128, nullptr, OFF_TPRE, 680,
                                         nullptr, 0, 0, 0, nullptr, nullptr, 0);
    iel_fused<<<dim3(BB * 340, 16), 128>>>(dw_w, dw1_w, dw2_w);

    // final: out = conv1x1(x12, pout_w) + xatt  (K=340 -> fp16 streaming GEMM)
    dim3 gg128(NP / 128, 1, BB);
    gemm_hstream<<<gg128, 256>>>(pout_w, OFF_X12, 340, out, 128, 340, OFF_XATT);
}